// round 6
// baseline (speedup 1.0000x reference)
#include <cuda_runtime.h>
#include <cstdint>

// ============================ constants ============================
#define NR        200               // number of masks
#define HW        200704            // 448*448
#define NTK       3136              // total K tiles of 64
#define GRID      148
#define NTHREADS  512
#define RS8       80                // s8 buffer row stride (64 data + 16 pad) — R3-proven
#define STAGE_B   51200             // 200 rows * 64 fp32
#define NSTAGE    3
#define BUF_B     (224*RS8)         // 17920
#define OFF_BUF   (NSTAGE*STAGE_B)  // 153600
#define DYN_SMEM  (NSTAGE*STAGE_B + 2*BUF_B)   // 189440
#define NTOUT     28                // upper-tri 32x32 tiles (7x7 grid)
#define NPART     (49*1024)         // scratch slab: full 7x7 tile grid

__device__ float g_scratch[(size_t)GRID * NPART];   // ~29.7 MB
__device__ float g_inter[NR * NR];
__device__ float g_comp[256];
__device__ unsigned g_count;
__device__ unsigned g_gen;

__device__ __constant__ unsigned char TIa[NTOUT] =
    {0,0,0,0,0,0,0, 1,1,1,1,1,1, 2,2,2,2,2, 3,3,3,3, 4,4,4, 5,5, 6};
__device__ __constant__ unsigned char TJa[NTOUT] =
    {0,1,2,3,4,5,6, 1,2,3,4,5,6, 2,3,4,5,6, 3,4,5,6, 4,5,6, 5,6, 6};

// per-warp gram jobs: 12 pairs (A-fragment shared across 2 tj) + 4 singles
__device__ __constant__ unsigned char JTI[16] = {0,0,0, 1,1,1, 2,2, 3,3, 4, 5, 0, 2, 4, 6};
__device__ __constant__ unsigned char JT0[16] = {0,2,4, 1,3,5, 2,4, 3,5, 4, 5, 6, 6, 6, 6};
__device__ __constant__ unsigned char JN [16] = {2,2,2, 2,2,2, 2,2, 2,2, 2, 2, 1, 1, 1, 1};

// ============================ helpers ============================
__device__ __forceinline__ uint32_t smem_u32(const void* p) {
    uint32_t a;
    asm("{ .reg .u64 t; cvta.to.shared.u64 t, %1; cvt.u32.u64 %0, t; }"
        : "=r"(a) : "l"(p));
    return a;
}

__device__ __forceinline__ void cp_async16(uint32_t sdst, const void* gsrc) {
    asm volatile("cp.async.cg.shared.global [%0], [%1], 16;"
                 :: "r"(sdst), "l"(gsrc) : "memory");
}
#define CP_COMMIT() asm volatile("cp.async.commit_group;" ::: "memory")
#define CP_WAIT(n)  asm volatile("cp.async.wait_group %0;" :: "n"(n) : "memory")

__device__ __forceinline__ void ldsm4(uint32_t* r, uint32_t addr) {
    asm volatile("ldmatrix.sync.aligned.m8n8.x4.shared.b16 {%0,%1,%2,%3}, [%4];"
                 : "=r"(r[0]), "=r"(r[1]), "=r"(r[2]), "=r"(r[3]) : "r"(addr));
}

// s8 IMMA, K=32, s32 accumulate (exact for 0/1 masks)
__device__ __forceinline__ void mma16832s(int* d, const uint32_t* a, const uint32_t* b) {
    asm volatile(
        "mma.sync.aligned.m16n8k32.row.col.s32.s8.s8.s32 "
        "{%0,%1,%2,%3}, {%4,%5,%6,%7}, {%8,%9}, {%0,%1,%2,%3};"
        : "+r"(d[0]), "+r"(d[1]), "+r"(d[2]), "+r"(d[3])
        : "r"(a[0]), "r"(a[1]), "r"(a[2]), "r"(a[3]), "r"(b[0]), "r"(b[1]));
}

// grid barrier: atomic arrivals, plain-load polling with nanosleep backoff
__device__ __forceinline__ void grid_barrier() {
    __syncthreads();
    if (threadIdx.x == 0) {
        __threadfence();
        unsigned gen = *(volatile unsigned*)&g_gen;
        unsigned arrived = atomicAdd(&g_count, 1u) + 1u;
        if (arrived == GRID) {
            atomicExch(&g_count, 0u);
            __threadfence();
            atomicAdd(&g_gen, 1u);
        } else {
            while (*(volatile unsigned*)&g_gen == gen) __nanosleep(128);
        }
        __threadfence();
    }
    __syncthreads();
}

__device__ __forceinline__ void issue_stage(uint32_t stage, const float* seg, int t, int tid) {
    const float* base = seg + (size_t)t * 64;
    #pragma unroll
    for (int it = 0; it < 6; it++) {
        int idx = tid + it * NTHREADS;
        int row = idx >> 4, c4 = idx & 15;
        cp_async16(stage + (uint32_t)idx * 16, base + (size_t)row * HW + c4 * 4);
    }
    if (tid < 128) {
        int idx = tid + 3072;
        int row = idx >> 4, c4 = idx & 15;
        cp_async16(stage + (uint32_t)idx * 16, base + (size_t)row * HW + c4 * 4);
    }
    CP_COMMIT();
}

// fp32 stage -> s8 buffer. 1.0f byte3 = 0x3F -> bit0 = 1; 0.0f -> 0.
__device__ __forceinline__ void convert_stage(char* smem, int stage_off, int buf_off, int tid) {
    #pragma unroll
    for (int it = 0; it < 7; it++) {
        int idx = tid + it * NTHREADS;
        if (idx < 3200) {
            int row = idx >> 4, c4 = idx & 15;
            float4 v = *reinterpret_cast<const float4*>(smem + stage_off + (size_t)idx * 16);
            uint32_t lo = __byte_perm(__float_as_uint(v.x), __float_as_uint(v.y), 0x0073);
            uint32_t hi = __byte_perm(__float_as_uint(v.z), __float_as_uint(v.w), 0x7300);
            uint32_t w = (lo | hi) & 0x01010101u;
            *reinterpret_cast<uint32_t*>(smem + buf_off + (size_t)row * RS8 + c4 * 4) = w;
        }
    }
}

// ============================ fused kernel ============================
__global__ __launch_bounds__(NTHREADS, 1)
void fused_kernel(const float* __restrict__ seg,
                  const float* __restrict__ scores,
                  const int* __restrict__ labels,
                  float* __restrict__ out) {
    extern __shared__ char smem[];
    const uint32_t sbase = smem_u32(smem);
    const int tid = threadIdx.x;
    const int wid = tid >> 5;
    const int lid = tid & 31;
    const int bid = blockIdx.x;

    // ================= phase 1: split-K Gram (s8 IMMA, A-fragment reuse) =================
    {
        const int t0 = (bid * NTK) / GRID;
        const int t1 = ((bid + 1) * NTK) / GRID;

        // zero pad rows 200..223 of both s8 buffers (written once)
        for (int i = tid; i < (24 * RS8) / 4; i += NTHREADS) {
            *reinterpret_cast<uint32_t*>(smem + OFF_BUF + 200 * RS8 + i * 4) = 0u;
            *reinterpret_cast<uint32_t*>(smem + OFF_BUF + BUF_B + 200 * RS8 + i * 4) = 0u;
        }

        const int ti  = JTI[wid];
        const int tj0 = JT0[wid];
        const int njt = JN[wid];

        int acc[2][2][4][4];
        #pragma unroll
        for (int a = 0; a < 2; a++)
            #pragma unroll
            for (int b = 0; b < 2; b++)
                #pragma unroll
                for (int c = 0; c < 4; c++)
                    #pragma unroll
                    for (int d = 0; d < 4; d++) acc[a][b][c][d] = 0;

        // ldmatrix lane offsets for s8 rows of RS8 bytes (R3-proven layout)
        const uint32_t aoff = (uint32_t)(lid & 15) * RS8 + (uint32_t)((lid >> 4) << 4);
        const uint32_t boff = (uint32_t)(((lid >> 4) << 3) + (lid & 7)) * RS8
                            + (uint32_t)(((lid >> 3) & 1) << 4);

        // prologue: fill up to 3 stages
        issue_stage(sbase + (uint32_t)((t0 % 3) * STAGE_B), seg, t0, tid);
        if (t0 + 1 < t1) issue_stage(sbase + (uint32_t)(((t0 + 1) % 3) * STAGE_B), seg, t0 + 1, tid);
        if (t0 + 2 < t1) issue_stage(sbase + (uint32_t)(((t0 + 2) % 3) * STAGE_B), seg, t0 + 2, tid);
        if (t0 + 2 < t1)      { CP_WAIT(2); }
        else if (t0 + 1 < t1) { CP_WAIT(1); }
        else                  { CP_WAIT(0); }
        convert_stage(smem, (t0 % 3) * STAGE_B, OFF_BUF + (t0 & 1) * BUF_B, tid);
        __syncthreads();

        for (int t = t0; t < t1; t++) {
            if (t + 3 < t1)
                issue_stage(sbase + (uint32_t)(((t + 3) % 3) * STAGE_B), seg, t + 3, tid);

            // compute tile t from s8 buf[t&1] : 2 K-steps of K=32
            const uint32_t buf = sbase + OFF_BUF + (uint32_t)((t & 1) * BUF_B);
            #pragma unroll
            for (int ks = 0; ks < 2; ks++) {
                const uint32_t koff = (uint32_t)ks * 32;   // 32 s8 = 32 bytes
                uint32_t afr[2][4];
                const uint32_t aA = buf + (uint32_t)(ti * 32) * RS8 + aoff + koff;
                ldsm4(afr[0], aA);
                ldsm4(afr[1], aA + 16 * RS8);
                #pragma unroll
                for (int nn = 0; nn < 2; nn++) {
                    if (nn < njt) {
                        uint32_t bfr[2][4];
                        const uint32_t aB = buf + (uint32_t)((tj0 + nn) * 32) * RS8 + boff + koff;
                        ldsm4(bfr[0], aB);
                        ldsm4(bfr[1], aB + 16 * RS8);
                        #pragma unroll
                        for (int mh = 0; mh < 2; mh++)
                            #pragma unroll
                            for (int nq = 0; nq < 4; nq++)
                                mma16832s(acc[nn][mh][nq], afr[mh], &bfr[nq >> 1][(nq & 1) * 2]);
                    }
                }
            }

            if (t + 1 < t1) {
                if (t + 3 < t1)      { CP_WAIT(2); }
                else if (t + 2 < t1) { CP_WAIT(1); }
                else                 { CP_WAIT(0); }
                convert_stage(smem, ((t + 1) % 3) * STAGE_B,
                              OFF_BUF + ((t + 1) & 1) * BUF_B, tid);
                __syncthreads();
            }
        }

        // epilogue: s32 -> fp32 partials -> scratch
        #pragma unroll
        for (int nn = 0; nn < 2; nn++) {
            if (nn < njt) {
                float* dst = g_scratch + (size_t)bid * NPART
                           + (size_t)(ti * 7 + (tj0 + nn)) * 1024;
                #pragma unroll
                for (int mh = 0; mh < 2; mh++) {
                    #pragma unroll
                    for (int nq = 0; nq < 4; nq++) {
                        const int r = mh * 16 + (lid >> 2);
                        const int c = nq * 8 + (lid & 3) * 2;
                        *reinterpret_cast<float2*>(dst + (size_t)r * 32 + c) =
                            make_float2(__int2float_rn(acc[nn][mh][nq][0]),
                                        __int2float_rn(acc[nn][mh][nq][1]));
                        *reinterpret_cast<float2*>(dst + (size_t)(r + 8) * 32 + c) =
                            make_float2(__int2float_rn(acc[nn][mh][nq][2]),
                                        __int2float_rn(acc[nn][mh][nq][3]));
                    }
                }
            }
        }
    }

    grid_barrier();

    // ================= phase 2: reduce split-K partials (all 148 CTAs) =================
    {
        float* sred = reinterpret_cast<float*>(smem);     // 256 floats
        const int gw = bid * 16 + wid;
        const int job = gw >> 1;
        const bool active = job < 896;
        float part = 0.f;
        int e = 0;
        if (active) {
            e = (job << 5) + lid;
            const int tl = e >> 10;
            const int off = ((int)TIa[tl] * 7 + (int)TJa[tl]) * 1024 + (e & 1023);
            const float* p = g_scratch + (size_t)((gw & 1) * 74) * NPART + off;
            float a = 0.f, b = 0.f;
            #pragma unroll
            for (int k = 0; k < 74; k += 2) {
                a += p[(size_t)k * NPART];
                b += p[(size_t)(k + 1) * NPART];
            }
            part = a + b;
        }
        if (active && (gw & 1)) sred[((wid >> 1) << 5) + lid] = part;
        __syncthreads();
        if (active && !(gw & 1)) {
            const float sum = part + sred[((wid >> 1) << 5) + lid];
            const int tl = e >> 10;
            const int gi = TIa[tl] * 32 + ((e >> 5) & 31);
            const int gj = TJa[tl] * 32 + (e & 31);
            if (gi < NR && gj < NR) g_inter[gi * NR + gj] = sum;
        }
    }

    grid_barrier();

    // ================= phase 3a: compensate IoU, one warp per j =================
    {
        const int j = bid * 16 + wid;
        if (j < NR) {
            const int lj = labels[j];
            const float sj = g_inter[j * NR + j];
            float m = 0.f;
            for (int i = lid; i < j; i += 32) {
                if (labels[i] == lj) {
                    const float in_ = g_inter[i * NR + j];
                    m = fmaxf(m, in_ / (g_inter[i * NR + i] + sj - in_));
                }
            }
            #pragma unroll
            for (int o = 16; o; o >>= 1) m = fmaxf(m, __shfl_xor_sync(~0u, m, o));
            if (lid == 0) g_comp[j] = m;
        }
    }

    grid_barrier();

    // ================= phase 3b: decay coefficient (min over ALL i) =================
    {
        const int j = bid * 16 + wid;
        if (j < NR) {
            const int lj = labels[j];
            const float sj = g_inter[j * NR + j];
            float mn = 3.4e38f;
            for (int i = lid; i < NR; i += 32) {
                float d = 0.f;
                if (i < j && labels[i] == lj) {
                    const float in_ = g_inter[i * NR + j];
                    d = in_ / (g_inter[i * NR + i] + sj - in_);
                }
                const float c = g_comp[i];
                mn = fminf(mn, c * c - d * d);
            }
            #pragma unroll
            for (int o = 16; o; o >>= 1) mn = fminf(mn, __shfl_xor_sync(~0u, mn, o));
            if (lid == 0) out[j] = scores[j] * expf(2.0f * mn);   // SIGMA = 2
        }
    }
}

// ============================ launch ============================
extern "C" void kernel_launch(void* const* d_in, const int* in_sizes, int n_in,
                              void* d_out, int out_size) {
    const float* seg    = (const float*)d_in[0];
    const float* scores = (const float*)d_in[1];
    const int*   labels = (const int*)d_in[2];
    float* out = (float*)d_out;

    cudaFuncSetAttribute(fused_kernel, cudaFuncAttributeMaxDynamicSharedMemorySize, DYN_SMEM);
    fused_kernel<<<GRID, NTHREADS, DYN_SMEM>>>(seg, scores, labels, out);
}

// round 7
// speedup vs baseline: 1.8584x; 1.8584x over previous
#include <cuda_runtime.h>
#include <cuda_bf16.h>
#include <cstdint>

// ============================ constants ============================
#define NR        200               // number of masks
#define HW        200704            // 448*448
#define NTK       3136              // total K tiles of 64
#define GRID      148
#define NTHREADS  512
#define ROWSTR    144               // bf16 buffer row stride in bytes (R2/R5-proven)
#define STAGE_B   51200             // 200 rows * 64 fp32
#define NSTAGE    3
#define BUF_B     (224*ROWSTR)      // 32256
#define OFF_BUF   (NSTAGE*STAGE_B)  // 153600
#define DYN_SMEM  (NSTAGE*STAGE_B + 2*BUF_B)   // 218112... too big? 153600+64512=218112 > 227KB ok? limit 232448 dyn; fits.
#define NTOUT     28                // upper-tri 32x32 tiles (7x7 grid)
#define NPART     (49*1024)         // slab elements (full 7x7 grid)

__device__ unsigned short g_scratch16[(size_t)GRID * NPART];   // ~14.8 MB, u16 partials (exact, <= 1792)
__device__ float g_inter[NR * NR];
__device__ float g_comp[256];
__device__ unsigned g_count;
__device__ unsigned g_gen;

__device__ __constant__ unsigned char TIa[NTOUT] =
    {0,0,0,0,0,0,0, 1,1,1,1,1,1, 2,2,2,2,2, 3,3,3,3, 4,4,4, 5,5, 6};
__device__ __constant__ unsigned char TJa[NTOUT] =
    {0,1,2,3,4,5,6, 1,2,3,4,5,6, 2,3,4,5,6, 3,4,5,6, 4,5,6, 5,6, 6};

// per-warp gram jobs: 12 pairs (A-fragment shared across 2 tj) + 4 singles
__device__ __constant__ unsigned char JTI[16] = {0,0,0, 1,1,1, 2,2, 3,3, 4, 5, 0, 2, 4, 6};
__device__ __constant__ unsigned char JT0[16] = {0,2,4, 1,3,5, 2,4, 3,5, 4, 5, 6, 6, 6, 6};
__device__ __constant__ unsigned char JN [16] = {2,2,2, 2,2,2, 2,2, 2,2, 2, 2, 1, 1, 1, 1};

// ============================ helpers ============================
__device__ __forceinline__ uint32_t smem_u32(const void* p) {
    uint32_t a;
    asm("{ .reg .u64 t; cvta.to.shared.u64 t, %1; cvt.u32.u64 %0, t; }"
        : "=r"(a) : "l"(p));
    return a;
}

__device__ __forceinline__ void cp_async16(uint32_t sdst, const void* gsrc) {
    asm volatile("cp.async.cg.shared.global [%0], [%1], 16;"
                 :: "r"(sdst), "l"(gsrc) : "memory");
}
#define CP_COMMIT() asm volatile("cp.async.commit_group;" ::: "memory")
#define CP_WAIT(n)  asm volatile("cp.async.wait_group %0;" :: "n"(n) : "memory")

__device__ __forceinline__ void ldsm4(uint32_t* r, uint32_t addr) {
    asm volatile("ldmatrix.sync.aligned.m8n8.x4.shared.b16 {%0,%1,%2,%3}, [%4];"
                 : "=r"(r[0]), "=r"(r[1]), "=r"(r[2]), "=r"(r[3]) : "r"(addr));
}

__device__ __forceinline__ void mma16816(float* d, const uint32_t* a, const uint32_t* b) {
    asm volatile(
        "mma.sync.aligned.m16n8k16.row.col.f32.bf16.bf16.f32 "
        "{%0,%1,%2,%3}, {%4,%5,%6,%7}, {%8,%9}, {%0,%1,%2,%3};"
        : "+f"(d[0]), "+f"(d[1]), "+f"(d[2]), "+f"(d[3])
        : "r"(a[0]), "r"(a[1]), "r"(a[2]), "r"(a[3]), "r"(b[0]), "r"(b[1]));
}

// grid barrier: atomic arrivals, plain-load polling with nanosleep backoff
__device__ __forceinline__ void grid_barrier() {
    __syncthreads();
    if (threadIdx.x == 0) {
        __threadfence();
        unsigned gen = *(volatile unsigned*)&g_gen;
        unsigned arrived = atomicAdd(&g_count, 1u) + 1u;
        if (arrived == GRID) {
            atomicExch(&g_count, 0u);
            __threadfence();
            atomicAdd(&g_gen, 1u);
        } else {
            while (*(volatile unsigned*)&g_gen == gen) __nanosleep(128);
        }
        __threadfence();
    }
    __syncthreads();
}

__device__ __forceinline__ void issue_stage(uint32_t stage, const float* seg, int t, int tid) {
    const float* base = seg + (size_t)t * 64;
    #pragma unroll
    for (int it = 0; it < 6; it++) {
        int idx = tid + it * NTHREADS;
        int row = idx >> 4, c4 = idx & 15;
        cp_async16(stage + (uint32_t)idx * 16, base + (size_t)row * HW + c4 * 4);
    }
    if (tid < 128) {
        int idx = tid + 3072;
        int row = idx >> 4, c4 = idx & 15;
        cp_async16(stage + (uint32_t)idx * 16, base + (size_t)row * HW + c4 * 4);
    }
    CP_COMMIT();
}

// convert a chunk of the fp32 stage -> bf16 buffer (iterations [it0, it1))
template<int IT0, int IT1>
__device__ __forceinline__ void convert_chunk(char* smem, int stage_off, int buf_off, int tid) {
    #pragma unroll
    for (int it = IT0; it < IT1; it++) {
        int idx = tid + it * NTHREADS;
        if (idx < 3200) {
            int row = idx >> 4, c4 = idx & 15;
            float4 v = *reinterpret_cast<const float4*>(smem + stage_off + (size_t)idx * 16);
            __nv_bfloat162 p0 = __floats2bfloat162_rn(v.x, v.y);
            __nv_bfloat162 p1 = __floats2bfloat162_rn(v.z, v.w);
            uint2 w;
            w.x = *reinterpret_cast<uint32_t*>(&p0);
            w.y = *reinterpret_cast<uint32_t*>(&p1);
            *reinterpret_cast<uint2*>(smem + buf_off + (size_t)row * ROWSTR + c4 * 8) = w;
        }
    }
}

// ============================ fused kernel ============================
__global__ __launch_bounds__(NTHREADS, 1)
void fused_kernel(const float* __restrict__ seg,
                  const float* __restrict__ scores,
                  const int* __restrict__ labels,
                  float* __restrict__ out) {
    extern __shared__ char smem[];
    const uint32_t sbase = smem_u32(smem);
    const int tid = threadIdx.x;
    const int wid = tid >> 5;
    const int lid = tid & 31;
    const int bid = blockIdx.x;

    // ================= phase 1: split-K Gram (bf16 mma, interleaved convert) =================
    {
        const int t0 = (bid * NTK) / GRID;
        const int t1 = ((bid + 1) * NTK) / GRID;

        // zero pad rows 200..223 of both bf16 buffers (written once)
        for (int i = tid; i < (24 * ROWSTR) / 4; i += NTHREADS) {
            *reinterpret_cast<uint32_t*>(smem + OFF_BUF + 200 * ROWSTR + i * 4) = 0u;
            *reinterpret_cast<uint32_t*>(smem + OFF_BUF + BUF_B + 200 * ROWSTR + i * 4) = 0u;
        }

        const int ti  = JTI[wid];
        const int tj0 = JT0[wid];
        const int njt = JN[wid];

        float acc[2][2][4][4];
        #pragma unroll
        for (int a = 0; a < 2; a++)
            #pragma unroll
            for (int b = 0; b < 2; b++)
                #pragma unroll
                for (int c = 0; c < 4; c++)
                    #pragma unroll
                    for (int d = 0; d < 4; d++) acc[a][b][c][d] = 0.f;

        const uint32_t aoff = (uint32_t)(lid & 15) * ROWSTR + (uint32_t)((lid >> 4) << 4);
        const uint32_t boff = (uint32_t)(((lid >> 4) << 3) + (lid & 7)) * ROWSTR
                            + (uint32_t)(((lid >> 3) & 1) << 4);

        // prologue: fill up to 3 stages, convert tile t0
        issue_stage(sbase + (uint32_t)((t0 % 3) * STAGE_B), seg, t0, tid);
        if (t0 + 1 < t1) issue_stage(sbase + (uint32_t)(((t0 + 1) % 3) * STAGE_B), seg, t0 + 1, tid);
        if (t0 + 2 < t1) issue_stage(sbase + (uint32_t)(((t0 + 2) % 3) * STAGE_B), seg, t0 + 2, tid);
        if (t0 + 2 < t1)      { CP_WAIT(2); }
        else if (t0 + 1 < t1) { CP_WAIT(1); }
        else                  { CP_WAIT(0); }
        convert_chunk<0, 7>(smem, (t0 % 3) * STAGE_B, OFF_BUF + (t0 & 1) * BUF_B, tid);
        __syncthreads();

        for (int t = t0; t < t1; t++) {
            const bool more1 = (t + 1 < t1);
            if (t + 3 < t1)
                issue_stage(sbase + (uint32_t)(((t + 3) % 3) * STAGE_B), seg, t + 3, tid);
            // ensure stage t+1 is resident before converting it below
            if (more1) {
                if (t + 3 < t1)      { CP_WAIT(2); }
                else if (t + 2 < t1) { CP_WAIT(1); }
                else                 { CP_WAIT(0); }
            }

            const uint32_t buf = sbase + OFF_BUF + (uint32_t)((t & 1) * BUF_B);
            const int nstage = ((t + 1) % 3) * STAGE_B;
            const int nbuf   = OFF_BUF + ((t + 1) & 1) * BUF_B;

            // ---- ksteps 0,1 of tile t ----
            #pragma unroll
            for (int ks = 0; ks < 2; ks++) {
                const uint32_t koff = (uint32_t)ks * 32;
                uint32_t afr[2][4];
                const uint32_t aA = buf + (uint32_t)(ti * 32) * ROWSTR + aoff + koff;
                ldsm4(afr[0], aA);
                ldsm4(afr[1], aA + 16 * ROWSTR);
                #pragma unroll
                for (int nn = 0; nn < 2; nn++) {
                    if (nn < njt) {
                        uint32_t bfr[2][4];
                        const uint32_t aB = buf + (uint32_t)((tj0 + nn) * 32) * ROWSTR + boff + koff;
                        ldsm4(bfr[0], aB);
                        ldsm4(bfr[1], aB + 16 * ROWSTR);
                        #pragma unroll
                        for (int mh = 0; mh < 2; mh++)
                            #pragma unroll
                            for (int nq = 0; nq < 4; nq++)
                                mma16816(acc[nn][mh][nq], afr[mh], &bfr[nq >> 1][(nq & 1) * 2]);
                    }
                }
            }

            // ---- convert(t+1) first half, overlapped with tensor work ----
            if (more1) convert_chunk<0, 4>(smem, nstage, nbuf, tid);

            // ---- ksteps 2,3 of tile t ----
            #pragma unroll
            for (int ks = 2; ks < 4; ks++) {
                const uint32_t koff = (uint32_t)ks * 32;
                uint32_t afr[2][4];
                const uint32_t aA = buf + (uint32_t)(ti * 32) * ROWSTR + aoff + koff;
                ldsm4(afr[0], aA);
                ldsm4(afr[1], aA + 16 * ROWSTR);
                #pragma unroll
                for (int nn = 0; nn < 2; nn++) {
                    if (nn < njt) {
                        uint32_t bfr[2][4];
                        const uint32_t aB = buf + (uint32_t)((tj0 + nn) * 32) * ROWSTR + boff + koff;
                        ldsm4(bfr[0], aB);
                        ldsm4(bfr[1], aB + 16 * ROWSTR);
                        #pragma unroll
                        for (int mh = 0; mh < 2; mh++)
                            #pragma unroll
                            for (int nq = 0; nq < 4; nq++)
                                mma16816(acc[nn][mh][nq], afr[mh], &bfr[nq >> 1][(nq & 1) * 2]);
                    }
                }
            }

            // ---- convert(t+1) second half ----
            if (more1) {
                convert_chunk<4, 7>(smem, nstage, nbuf, tid);
                __syncthreads();
            }
        }

        // epilogue: u16 partials -> scratch (values <= 1792, exact)
        #pragma unroll
        for (int nn = 0; nn < 2; nn++) {
            if (nn < njt) {
                unsigned short* dst = g_scratch16 + (size_t)bid * NPART
                                    + (size_t)(ti * 7 + (tj0 + nn)) * 1024;
                #pragma unroll
                for (int mh = 0; mh < 2; mh++) {
                    #pragma unroll
                    for (int nq = 0; nq < 4; nq++) {
                        const int r = mh * 16 + (lid >> 2);
                        const int c = nq * 8 + (lid & 3) * 2;
                        uint32_t w0 = (uint32_t)(int)acc[nn][mh][nq][0]
                                    | ((uint32_t)(int)acc[nn][mh][nq][1] << 16);
                        uint32_t w1 = (uint32_t)(int)acc[nn][mh][nq][2]
                                    | ((uint32_t)(int)acc[nn][mh][nq][3] << 16);
                        *reinterpret_cast<uint32_t*>(dst + (size_t)r * 32 + c) = w0;
                        *reinterpret_cast<uint32_t*>(dst + (size_t)(r + 8) * 32 + c) = w1;
                    }
                }
            }
        }
    }

    grid_barrier();

    // ================= phase 2: reduce u16 split-K partials =================
    // 448 jobs of 64 elements (32 u32 words); 2 warps/job (74 slabs each), smem combine.
    {
        int2* sred = reinterpret_cast<int2*>(smem);       // 256 int2
        const int gw = bid * 16 + wid;
        const int job = gw >> 1;
        const bool active = job < 448;
        int sa = 0, sb = 0;
        int e2 = 0;
        if (active) {
            e2 = (job << 6) + (lid << 1);                 // even element index
            const int tl = e2 >> 10;
            const int off = ((int)TIa[tl] * 7 + (int)TJa[tl]) * 1024 + (e2 & 1023);
            const unsigned short* p = g_scratch16 + (size_t)((gw & 1) * 74) * NPART + off;
            #pragma unroll
            for (int k = 0; k < 74; k++) {
                const uint32_t w = *reinterpret_cast<const uint32_t*>(p + (size_t)k * NPART);
                sa += (int)(w & 0xFFFFu);
                sb += (int)(w >> 16);
            }
        }
        if (active && (gw & 1)) sred[((wid >> 1) << 5) + lid] = make_int2(sa, sb);
        __syncthreads();
        if (active && !(gw & 1)) {
            const int2 o = sred[((wid >> 1) << 5) + lid];
            const int tl = e2 >> 10;
            const int gi = TIa[tl] * 32 + ((e2 >> 5) & 31);
            const int gj = TJa[tl] * 32 + (e2 & 31);
            if (gi < NR && gj < NR) {
                g_inter[gi * NR + gj] = (float)(sa + o.x);
                if (gj + 1 < NR) g_inter[gi * NR + gj + 1] = (float)(sb + o.y);
            }
        }
    }

    grid_barrier();

    // ================= phase 3a: compensate IoU, one warp per j =================
    {
        const int j = bid * 16 + wid;
        if (j < NR) {
            const int lj = labels[j];
            const float sj = g_inter[j * NR + j];
            float m = 0.f;
            for (int i = lid; i < j; i += 32) {
                if (labels[i] == lj) {
                    const float in_ = g_inter[i * NR + j];
                    m = fmaxf(m, in_ / (g_inter[i * NR + i] + sj - in_));
                }
            }
            #pragma unroll
            for (int o = 16; o; o >>= 1) m = fmaxf(m, __shfl_xor_sync(~0u, m, o));
            if (lid == 0) g_comp[j] = m;
        }
    }

    grid_barrier();

    // ================= phase 3b: decay coefficient (min over ALL i) =================
    {
        const int j = bid * 16 + wid;
        if (j < NR) {
            const int lj = labels[j];
            const float sj = g_inter[j * NR + j];
            float mn = 3.4e38f;
            for (int i = lid; i < NR; i += 32) {
                float d = 0.f;
                if (i < j && labels[i] == lj) {
                    const float in_ = g_inter[i * NR + j];
                    d = in_ / (g_inter[i * NR + i] + sj - in_);
                }
                const float c = g_comp[i];
                mn = fminf(mn, c * c - d * d);
            }
            #pragma unroll
            for (int o = 16; o; o >>= 1) mn = fminf(mn, __shfl_xor_sync(~0u, mn, o));
            if (lid == 0) out[j] = scores[j] * expf(2.0f * mn);   // SIGMA = 2
        }
    }
}

// ============================ launch ============================
extern "C" void kernel_launch(void* const* d_in, const int* in_sizes, int n_in,
                              void* d_out, int out_size) {
    const float* seg    = (const float*)d_in[0];
    const float* scores = (const float*)d_in[1];
    const int*   labels = (const int*)d_in[2];
    float* out = (float*)d_out;

    cudaFuncSetAttribute(fused_kernel, cudaFuncAttributeMaxDynamicSharedMemorySize, DYN_SMEM);
    fused_kernel<<<GRID, NTHREADS, DYN_SMEM>>>(seg, scores, labels, out);
}